// round 2
// baseline (speedup 1.0000x reference)
#include <cuda_runtime.h>
#include <math.h>

#define T_TOK 4096
#define CDIM  1024
#define HDIM  4096
#define EDIM  8

// ---- device scratch (allocation-free; __device__ globals are the sanctioned path) ----
__device__ float g_gate_sums[EDIM];
__device__ int   g_cnt[EDIM];
__device__ int   g_bucket_tok[EDIM * T_TOK];
__device__ int   g_pair_slot[T_TOK * 2];
__device__ float g_pair_gate[T_TOK * 2];
__device__ float g_H[(size_t)EDIM * T_TOK * HDIM];  // 512 MB capacity layout [E][4096][H]
__device__ float g_Y[(size_t)EDIM * T_TOK * CDIM];  // 128 MB

// ---------------------------------------------------------------------------
__global__ void init_kernel() {
    int i = threadIdx.x;
    if (i < EDIM) { g_gate_sums[i] = 0.0f; g_cnt[i] = 0; }
}

// One block (128 threads) per token: logits, gumbel-softmax, top-2, bucketing.
__global__ void gate_kernel(const float* __restrict__ x,
                            const float* __restrict__ gumbel,
                            const float* __restrict__ gw,
                            const float* __restrict__ gb) {
    const int t   = blockIdx.x;
    const int tid = threadIdx.x;

    float acc[EDIM];
#pragma unroll
    for (int e = 0; e < EDIM; e++) acc[e] = 0.0f;

    const float* xr = x + (size_t)t * CDIM;
    for (int i = tid; i < CDIM; i += 128) {
        float xv = xr[i];
#pragma unroll
        for (int e = 0; e < EDIM; e++) acc[e] += xv * gw[i * EDIM + e];
    }

    __shared__ float red[128][EDIM];
#pragma unroll
    for (int e = 0; e < EDIM; e++) red[tid][e] = acc[e];
    __syncthreads();
    for (int s = 64; s > 0; s >>= 1) {
        if (tid < s) {
#pragma unroll
            for (int e = 0; e < EDIM; e++) red[tid][e] += red[tid + s][e];
        }
        __syncthreads();
    }

    if (tid == 0) {
        float l[EDIM];
        float mx = -1e30f;
#pragma unroll
        for (int e = 0; e < EDIM; e++) {
            l[e] = red[0][e] + gb[e] + gumbel[t * EDIM + e];  // TAU = 1
            mx = fmaxf(mx, l[e]);
        }
        float sum = 0.0f;
#pragma unroll
        for (int e = 0; e < EDIM; e++) { l[e] = expf(l[e] - mx); sum += l[e]; }
        float inv = 1.0f / sum;
        float g[EDIM];
#pragma unroll
        for (int e = 0; e < EDIM; e++) {
            g[e] = l[e] * inv;
            atomicAdd(&g_gate_sums[e], g[e]);
        }
        // top-2
        int i0 = 0;
#pragma unroll
        for (int e = 1; e < EDIM; e++) if (g[e] > g[i0]) i0 = e;
        int i1 = (i0 == 0) ? 1 : 0;
#pragma unroll
        for (int e = 0; e < EDIM; e++) if (e != i0 && g[e] > g[i1]) i1 = e;

        int p0 = atomicAdd(&g_cnt[i0], 1);
        g_bucket_tok[i0 * T_TOK + p0] = t;
        g_pair_slot[t * 2 + 0] = i0 * T_TOK + p0;
        g_pair_gate[t * 2 + 0] = g[i0];

        int p1 = atomicAdd(&g_cnt[i1], 1);
        g_bucket_tok[i1 * T_TOK + p1] = t;
        g_pair_slot[t * 2 + 1] = i1 * T_TOK + p1;
        g_pair_gate[t * 2 + 1] = g[i1];
    }
}

// ---------------------------------------------------------------------------
// GEMM1: per expert, gathered X[Te,1024] @ w1[e][1024,4096] + b1, exact GELU -> g_H
// 64x64 tile, BK=16, 128 threads, 8x4 microtile.
__global__ __launch_bounds__(128) void gemm1_kernel(const float* __restrict__ x,
                                                    const float* __restrict__ w1,
                                                    const float* __restrict__ b1) {
    const int e  = blockIdx.z;
    const int m0 = blockIdx.y * 64;
    const int n0 = blockIdx.x * 64;
    const int cnt = g_cnt[e];
    if (m0 >= cnt) return;

    __shared__ __align__(16) float As[16][72];
    __shared__ __align__(16) float Bs[16][64];

    const int tid = threadIdx.x;
    const int tx = tid & 15;   // col group (x4)
    const int ty = tid >> 4;   // row group (x8)

    // two A-load quads per thread
    int arow[2], akq[2], tok[2];
#pragma unroll
    for (int l = 0; l < 2; l++) {
        int q = tid * 2 + l;
        arow[l] = q >> 2;
        akq[l]  = q & 3;
        int rg = m0 + arow[l];
        tok[l] = g_bucket_tok[e * T_TOK + ((rg < cnt) ? rg : (cnt - 1))];
    }

    const float* wbase = w1 + (size_t)e * CDIM * HDIM;

    float acc[8][4];
#pragma unroll
    for (int i = 0; i < 8; i++)
#pragma unroll
        for (int j = 0; j < 4; j++) acc[i][j] = 0.0f;

    for (int k0 = 0; k0 < CDIM; k0 += 16) {
#pragma unroll
        for (int l = 0; l < 2; l++) {
            float4 av = *reinterpret_cast<const float4*>(
                x + (size_t)tok[l] * CDIM + k0 + akq[l] * 4);
            As[akq[l] * 4 + 0][arow[l]] = av.x;
            As[akq[l] * 4 + 1][arow[l]] = av.y;
            As[akq[l] * 4 + 2][arow[l]] = av.z;
            As[akq[l] * 4 + 3][arow[l]] = av.w;
        }
#pragma unroll
        for (int l = 0; l < 2; l++) {
            int q = tid * 2 + l;
            int r = q >> 4, c4 = q & 15;
            float4 bv = *reinterpret_cast<const float4*>(
                wbase + (size_t)(k0 + r) * HDIM + n0 + c4 * 4);
            *reinterpret_cast<float4*>(&Bs[r][c4 * 4]) = bv;
        }
        __syncthreads();
#pragma unroll
        for (int k = 0; k < 16; k++) {
            float4 a0 = *reinterpret_cast<const float4*>(&As[k][ty * 8]);
            float4 a1 = *reinterpret_cast<const float4*>(&As[k][ty * 8 + 4]);
            float4 b  = *reinterpret_cast<const float4*>(&Bs[k][tx * 4]);
            float av[8] = {a0.x, a0.y, a0.z, a0.w, a1.x, a1.y, a1.z, a1.w};
            float bv[4] = {b.x, b.y, b.z, b.w};
#pragma unroll
            for (int i = 0; i < 8; i++)
#pragma unroll
                for (int j = 0; j < 4; j++) acc[i][j] += av[i] * bv[j];
        }
        __syncthreads();
    }

    // epilogue: +b1, exact GELU, store
    float4 bb = *reinterpret_cast<const float4*>(b1 + (size_t)e * HDIM + n0 + tx * 4);
#pragma unroll
    for (int i = 0; i < 8; i++) {
        int rg = m0 + ty * 8 + i;
        if (rg >= cnt) continue;
        int slot = e * T_TOK + rg;
        float v0 = acc[i][0] + bb.x;
        float v1 = acc[i][1] + bb.y;
        float v2 = acc[i][2] + bb.z;
        float v3 = acc[i][3] + bb.w;
        float4 o;
        o.x = 0.5f * v0 * (1.0f + erff(v0 * 0.70710678118654752f));
        o.y = 0.5f * v1 * (1.0f + erff(v1 * 0.70710678118654752f));
        o.z = 0.5f * v2 * (1.0f + erff(v2 * 0.70710678118654752f));
        o.w = 0.5f * v3 * (1.0f + erff(v3 * 0.70710678118654752f));
        *reinterpret_cast<float4*>(&g_H[(size_t)slot * HDIM + n0 + tx * 4]) = o;
    }
}

// ---------------------------------------------------------------------------
// GEMM2: per expert, H[Te,4096] @ w2[e][4096,1024] + b2 -> g_Y
__global__ __launch_bounds__(128) void gemm2_kernel(const float* __restrict__ w2,
                                                    const float* __restrict__ b2) {
    const int e  = blockIdx.z;
    const int m0 = blockIdx.y * 64;
    const int n0 = blockIdx.x * 64;
    const int cnt = g_cnt[e];
    if (m0 >= cnt) return;

    __shared__ __align__(16) float As[16][72];
    __shared__ __align__(16) float Bs[16][64];

    const int tid = threadIdx.x;
    const int tx = tid & 15;
    const int ty = tid >> 4;

    int arow[2], akq[2], slotA[2];
#pragma unroll
    for (int l = 0; l < 2; l++) {
        int q = tid * 2 + l;
        arow[l] = q >> 2;
        akq[l]  = q & 3;
        int rg = m0 + arow[l];
        slotA[l] = e * T_TOK + ((rg < cnt) ? rg : (cnt - 1));
    }

    const float* wbase = w2 + (size_t)e * HDIM * CDIM;

    float acc[8][4];
#pragma unroll
    for (int i = 0; i < 8; i++)
#pragma unroll
        for (int j = 0; j < 4; j++) acc[i][j] = 0.0f;

    for (int k0 = 0; k0 < HDIM; k0 += 16) {
#pragma unroll
        for (int l = 0; l < 2; l++) {
            float4 av = *reinterpret_cast<const float4*>(
                &g_H[(size_t)slotA[l] * HDIM + k0 + akq[l] * 4]);
            As[akq[l] * 4 + 0][arow[l]] = av.x;
            As[akq[l] * 4 + 1][arow[l]] = av.y;
            As[akq[l] * 4 + 2][arow[l]] = av.z;
            As[akq[l] * 4 + 3][arow[l]] = av.w;
        }
#pragma unroll
        for (int l = 0; l < 2; l++) {
            int q = tid * 2 + l;
            int r = q >> 4, c4 = q & 15;
            float4 bv = *reinterpret_cast<const float4*>(
                wbase + (size_t)(k0 + r) * CDIM + n0 + c4 * 4);
            *reinterpret_cast<float4*>(&Bs[r][c4 * 4]) = bv;
        }
        __syncthreads();
#pragma unroll
        for (int k = 0; k < 16; k++) {
            float4 a0 = *reinterpret_cast<const float4*>(&As[k][ty * 8]);
            float4 a1 = *reinterpret_cast<const float4*>(&As[k][ty * 8 + 4]);
            float4 b  = *reinterpret_cast<const float4*>(&Bs[k][tx * 4]);
            float av[8] = {a0.x, a0.y, a0.z, a0.w, a1.x, a1.y, a1.z, a1.w};
            float bv[4] = {b.x, b.y, b.z, b.w};
#pragma unroll
            for (int i = 0; i < 8; i++)
#pragma unroll
                for (int j = 0; j < 4; j++) acc[i][j] += av[i] * bv[j];
        }
        __syncthreads();
    }

    float4 bb = *reinterpret_cast<const float4*>(b2 + (size_t)e * CDIM + n0 + tx * 4);
#pragma unroll
    for (int i = 0; i < 8; i++) {
        int rg = m0 + ty * 8 + i;
        if (rg >= cnt) continue;
        int slot = e * T_TOK + rg;
        float4 o;
        o.x = acc[i][0] + bb.x;
        o.y = acc[i][1] + bb.y;
        o.z = acc[i][2] + bb.z;
        o.w = acc[i][3] + bb.w;
        *reinterpret_cast<float4*>(&g_Y[(size_t)slot * CDIM + n0 + tx * 4]) = o;
    }
}

// ---------------------------------------------------------------------------
__global__ void combine_kernel(float* __restrict__ out) {
    const int t = blockIdx.x;
    const int c = threadIdx.x * 4;  // 256 threads cover 1024 cols
    int   s0 = g_pair_slot[t * 2 + 0];
    int   s1 = g_pair_slot[t * 2 + 1];
    float g0 = g_pair_gate[t * 2 + 0];
    float g1 = g_pair_gate[t * 2 + 1];
    float4 y0 = *reinterpret_cast<const float4*>(&g_Y[(size_t)s0 * CDIM + c]);
    float4 y1 = *reinterpret_cast<const float4*>(&g_Y[(size_t)s1 * CDIM + c]);
    float4 o;
    o.x = g0 * y0.x + g1 * y1.x;
    o.y = g0 * y0.y + g1 * y1.y;
    o.z = g0 * y0.z + g1 * y1.z;
    o.w = g0 * y0.w + g1 * y1.w;
    *reinterpret_cast<float4*>(&out[(size_t)t * CDIM + c]) = o;
}

__global__ void loss_kernel(float* __restrict__ out, int out_size) {
    if (threadIdx.x == 0 && out_size > T_TOK * CDIM) {
        float l = 0.0f;
#pragma unroll
        for (int e = 0; e < EDIM; e++) {
            float m = g_gate_sums[e] / (float)T_TOK;
            l += m * logf(m + 1e-8f);
        }
        out[T_TOK * CDIM] = l;
    }
}

// ---------------------------------------------------------------------------
extern "C" void kernel_launch(void* const* d_in, const int* in_sizes, int n_in,
                              void* d_out, int out_size) {
    const float* x      = (const float*)d_in[0];
    const float* gumbel = (const float*)d_in[1];
    const float* gate_w = (const float*)d_in[2];
    const float* gate_b = (const float*)d_in[3];
    const float* w1     = (const float*)d_in[4];
    const float* b1     = (const float*)d_in[5];
    const float* w2     = (const float*)d_in[6];
    const float* b2     = (const float*)d_in[7];
    float* out = (float*)d_out;

    init_kernel<<<1, 32>>>();
    gate_kernel<<<T_TOK, 128>>>(x, gumbel, gate_w, gate_b);
    gemm1_kernel<<<dim3(HDIM / 64, T_TOK / 64, EDIM), 128>>>(x, w1, b1);
    gemm2_kernel<<<dim3(CDIM / 64, T_TOK / 64, EDIM), 128>>>(w2, b2);
    combine_kernel<<<T_TOK, 256>>>(out);
    loss_kernel<<<1, 32>>>(out, out_size);
}

// round 5
// speedup vs baseline: 2.5133x; 2.5133x over previous
#include <cuda_runtime.h>
#include <cuda_fp16.h>
#include <math.h>
#include <stdint.h>

#define T_TOK 4096
#define CDIM  1024
#define HDIM  4096
#define EDIM  8

// ---------------- device scratch (allocation-free) ----------------
__device__ float  g_gate_sums[EDIM];
__device__ int    g_cnt[EDIM];
__device__ int    g_bucket_tok[EDIM * T_TOK];
__device__ int    g_pair_slot[T_TOK * 2];
__device__ float  g_pair_gate[T_TOK * 2];
__device__ __half g_Ah [(size_t)EDIM * T_TOK * 2048];   // gathered x: hi[0,1024) lo[1024,2048)
__device__ __half g_Hh [(size_t)EDIM * T_TOK * 8192];   // gelu(h):    hi[0,4096) lo[4096,8192)
__device__ __half g_W1t[(size_t)EDIM * HDIM  * 2048];   // w1^T: [E][H][2048] hi|lo
__device__ __half g_W2t[(size_t)EDIM * CDIM  * 8192];   // w2^T: [E][C][8192] hi|lo
__device__ float  g_Y  [(size_t)EDIM * T_TOK * CDIM];

// ---------------- helpers ----------------
__device__ __forceinline__ uint32_t smem_u32(const void* p) {
    uint32_t a;
    asm("{ .reg .u64 t; cvta.to.shared.u64 t, %1; cvt.u32.u64 %0, t; }" : "=r"(a) : "l"(p));
    return a;
}
__device__ __forceinline__ void cp_async16(uint32_t dst, const void* src) {
    asm volatile("cp.async.cg.shared.global [%0], [%1], 16;\n" :: "r"(dst), "l"(src));
}
#define CP_COMMIT() asm volatile("cp.async.commit_group;" ::: "memory")
#define CP_WAIT1()  asm volatile("cp.async.wait_group 1;" ::: "memory")

__device__ __forceinline__ void ldmx4(uint32_t& r0, uint32_t& r1, uint32_t& r2, uint32_t& r3,
                                      uint32_t addr) {
    asm volatile("ldmatrix.sync.aligned.m8n8.x4.shared.b16 {%0,%1,%2,%3}, [%4];"
                 : "=r"(r0), "=r"(r1), "=r"(r2), "=r"(r3) : "r"(addr));
}
__device__ __forceinline__ void mma16816(float* d, const uint32_t* a, uint32_t b0, uint32_t b1) {
    asm volatile("mma.sync.aligned.m16n8k16.row.col.f32.f16.f16.f32 "
                 "{%0,%1,%2,%3}, {%4,%5,%6,%7}, {%8,%9}, {%0,%1,%2,%3};"
                 : "+f"(d[0]), "+f"(d[1]), "+f"(d[2]), "+f"(d[3])
                 : "r"(a[0]), "r"(a[1]), "r"(a[2]), "r"(a[3]), "r"(b0), "r"(b1));
}
// byte offset in a [128 rows][32 halves] tile; 16B chunk swizzle: c ^= (r>>1)&3
__device__ __forceinline__ uint32_t sma(int r, int c) {
    return (uint32_t)(((r << 2) | (c ^ ((r >> 1) & 3))) << 4);
}

// ---------------------------------------------------------------------------
__global__ void init_kernel() {
    int i = threadIdx.x;
    if (i < EDIM) { g_gate_sums[i] = 0.0f; g_cnt[i] = 0; }
}

__global__ void gate_kernel(const float* __restrict__ x,
                            const float* __restrict__ gumbel,
                            const float* __restrict__ gw,
                            const float* __restrict__ gb) {
    const int t = blockIdx.x, tid = threadIdx.x;
    float acc[EDIM];
#pragma unroll
    for (int e = 0; e < EDIM; e++) acc[e] = 0.0f;
    const float* xr = x + (size_t)t * CDIM;
    for (int i = tid; i < CDIM; i += 128) {
        float xv = xr[i];
#pragma unroll
        for (int e = 0; e < EDIM; e++) acc[e] += xv * gw[i * EDIM + e];
    }
    __shared__ float red[128][EDIM];
#pragma unroll
    for (int e = 0; e < EDIM; e++) red[tid][e] = acc[e];
    __syncthreads();
    for (int s = 64; s > 0; s >>= 1) {
        if (tid < s) {
#pragma unroll
            for (int e = 0; e < EDIM; e++) red[tid][e] += red[tid + s][e];
        }
        __syncthreads();
    }
    if (tid == 0) {
        float l[EDIM]; float mx = -1e30f;
#pragma unroll
        for (int e = 0; e < EDIM; e++) {
            l[e] = red[0][e] + gb[e] + gumbel[t * EDIM + e];
            mx = fmaxf(mx, l[e]);
        }
        float sum = 0.0f;
#pragma unroll
        for (int e = 0; e < EDIM; e++) { l[e] = expf(l[e] - mx); sum += l[e]; }
        float inv = 1.0f / sum;
        float g[EDIM];
#pragma unroll
        for (int e = 0; e < EDIM; e++) { g[e] = l[e] * inv; atomicAdd(&g_gate_sums[e], g[e]); }
        int i0 = 0;
#pragma unroll
        for (int e = 1; e < EDIM; e++) if (g[e] > g[i0]) i0 = e;
        int i1 = (i0 == 0) ? 1 : 0;
#pragma unroll
        for (int e = 0; e < EDIM; e++) if (e != i0 && g[e] > g[i1]) i1 = e;
        int p0 = atomicAdd(&g_cnt[i0], 1);
        g_bucket_tok[i0 * T_TOK + p0] = t;
        g_pair_slot[t * 2 + 0] = i0 * T_TOK + p0;
        g_pair_gate[t * 2 + 0] = g[i0];
        int p1 = atomicAdd(&g_cnt[i1], 1);
        g_bucket_tok[i1 * T_TOK + p1] = t;
        g_pair_slot[t * 2 + 1] = i1 * T_TOK + p1;
        g_pair_gate[t * 2 + 1] = g[i1];
    }
}

// gather x rows per expert slot -> fp16 hi|lo (zero-pad to 256-row boundary)
__global__ void convert_x_kernel(const float* __restrict__ x) {
    const int e = blockIdx.y, s = blockIdx.x;
    const int cnt = g_cnt[e];
    const int padded = (cnt + 255) & ~255;
    if (s >= padded) return;
    __half* dst = g_Ah + (size_t)(e * T_TOK + s) * 2048;
    const int t = threadIdx.x;  // 256 threads x 4 floats
    if (s < cnt) {
        int tok = g_bucket_tok[e * T_TOK + s];
        float4 v = ((const float4*)(x + (size_t)tok * CDIM))[t];
        __half h0 = __float2half_rn(v.x), h1 = __float2half_rn(v.y);
        __half h2 = __float2half_rn(v.z), h3 = __float2half_rn(v.w);
        ((__half2*)dst)[2 * t + 0] = __halves2half2(h0, h1);
        ((__half2*)dst)[2 * t + 1] = __halves2half2(h2, h3);
        __half l0 = __float2half_rn(v.x - __half2float(h0));
        __half l1 = __float2half_rn(v.y - __half2float(h1));
        __half l2 = __float2half_rn(v.z - __half2float(h2));
        __half l3 = __float2half_rn(v.w - __half2float(h3));
        ((__half2*)(dst + 1024))[2 * t + 0] = __halves2half2(l0, l1);
        ((__half2*)(dst + 1024))[2 * t + 1] = __halves2half2(l2, l3);
    } else {
        __half2 z = __halves2half2(__float2half_rn(0.f), __float2half_rn(0.f));
        ((__half2*)dst)[2 * t + 0] = z;
        ((__half2*)dst)[2 * t + 1] = z;
        ((__half2*)(dst + 1024))[2 * t + 0] = z;
        ((__half2*)(dst + 1024))[2 * t + 1] = z;
    }
}

// transpose + hi/lo split: in [E][A][Bd] fp32 -> out [E][Bd][2A] fp16 (hi | lo)
__global__ void convert_w_kernel(const float* __restrict__ W, int A, int Bd, int which) {
    __shared__ float s[32][33];
    const int e = blockIdx.z;
    const int a0 = blockIdx.y * 32, b0 = blockIdx.x * 32;
    const int tx = threadIdx.x, ty = threadIdx.y;  // (32, 8)
    const float* Wp = W + (size_t)e * A * Bd;
    __half* Wt = (which ? g_W2t : g_W1t) + (size_t)e * A * Bd * 2;
#pragma unroll
    for (int i = 0; i < 4; i++)
        s[ty * 4 + i][tx] = Wp[(size_t)(a0 + ty * 4 + i) * Bd + b0 + tx];
    __syncthreads();
#pragma unroll
    for (int i = 0; i < 4; i++) {
        float v = s[tx][ty * 4 + i];
        __half hi = __float2half_rn(v);
        __half lo = __float2half_rn(v - __half2float(hi));
        size_t row = (size_t)(b0 + ty * 4 + i) * (2 * A);
        Wt[row + a0 + tx]     = hi;
        Wt[row + A + a0 + tx] = lo;
    }
}

// ---------------------------------------------------------------------------
// HMMA grouped GEMM: BM=128, BN=128, BK=32, 256 threads (8 warps, 64x32 warp tiles).
// K' = 3*K region remap: r0 Ah*Bh, r1 Ah*Bl, r2 Al*Bh.
template<bool GELU, int KB>   // KB = K/32 iters per region
__global__ __launch_bounds__(256, 2) void gemm_hmma(const float* __restrict__ bias) {
    const int e = blockIdx.z;
    const int cnt = g_cnt[e];
    const int m0 = blockIdx.y * 128;
    if (m0 >= cnt) return;
    const int n0 = blockIdx.x * 128;
    const int NK = 3 * KB;

    const int SA   = GELU ? 2048 : 8192;   // row stride (halves), same for A and B
    const int LOFF = GELU ? 1024 : 4096;   // lo-plane offset
    const int NTOT = GELU ? HDIM : CDIM;
    const __half* __restrict__ abase = GELU ? g_Ah  : g_Hh;
    const __half* __restrict__ bbase = GELU ? g_W1t : g_W2t;

    __shared__ __align__(16) __half smA[3][128 * 32];
    __shared__ __align__(16) __half smB[3][128 * 32];
    const uint32_t aB = smem_u32(&smA[0][0]);
    const uint32_t bB = smem_u32(&smB[0][0]);

    const int tid  = threadIdx.x;
    const int lane = tid & 31;
    const int w    = tid >> 5;
    const int wm   = w & 1;        // 2 m-halves of 64
    const int wn   = w >> 1;       // 4 n-quarters of 32

    const __half* A0 = abase + (size_t)(e * T_TOK + m0) * SA;
    const __half* B0 = bbase + ((size_t)e * NTOT + n0) * SA;

    float acc[4][4][4];
#pragma unroll
    for (int i = 0; i < 4; i++)
#pragma unroll
        for (int j = 0; j < 4; j++)
#pragma unroll
            for (int q = 0; q < 4; q++) acc[i][j][q] = 0.0f;

    auto load_stage = [&](int kc) {
        const int rg  = kc / KB;
        const int kcl = kc - rg * KB;
        const int ao  = (rg == 2) ? LOFF : 0;
        const int bo  = (rg == 1) ? LOFF : 0;
        const int st  = kc % 3;
        const __half* ap = A0 + kcl * 32 + ao;
        const __half* bp = B0 + kcl * 32 + bo;
        const uint32_t aS = aB + st * 8192;
        const uint32_t bS = bB + st * 8192;
#pragma unroll
        for (int h = 0; h < 2; h++) {
            int id = tid + h * 256;
            int row = id >> 2, c = id & 3;
            cp_async16(aS + sma(row, c), ap + (size_t)row * SA + c * 8);
            cp_async16(bS + sma(row, c), bp + (size_t)row * SA + c * 8);
        }
    };

    load_stage(0); CP_COMMIT();
    load_stage(1); CP_COMMIT();

#pragma unroll 1
    for (int kc = 0; kc < NK; kc++) {
        const int s = kc % 3;
        CP_WAIT1();
        __syncthreads();
        if (kc + 2 < NK) load_stage(kc + 2);
        CP_COMMIT();

        const uint32_t aS = aB + s * 8192;
        const uint32_t bS = bB + s * 8192;
#pragma unroll
        for (int ks = 0; ks < 2; ks++) {
            uint32_t afr[4][4];
#pragma unroll
            for (int mi = 0; mi < 4; mi++) {
                int row = wm * 64 + mi * 16 + ((lane >> 3) & 1) * 8 + (lane & 7);
                int ch  = ks * 2 + (lane >> 4);
                ldmx4(afr[mi][0], afr[mi][1], afr[mi][2], afr[mi][3], aS + sma(row, ch));
            }
            uint32_t bfr[2][4];
#pragma unroll
            for (int nj = 0; nj < 2; nj++) {
                int row = wn * 32 + nj * 16 + (lane >> 4) * 8 + (lane & 7);
                int ch  = ks * 2 + ((lane >> 3) & 1);
                ldmx4(bfr[nj][0], bfr[nj][1], bfr[nj][2], bfr[nj][3], bS + sma(row, ch));
            }
#pragma unroll
            for (int mi = 0; mi < 4; mi++)
#pragma unroll
                for (int nj = 0; nj < 2; nj++) {
                    mma16816(acc[mi][nj * 2 + 0], afr[mi], bfr[nj][0], bfr[nj][1]);
                    mma16816(acc[mi][nj * 2 + 1], afr[mi], bfr[nj][2], bfr[nj][3]);
                }
        }
        __syncthreads();
    }

    // ---- epilogue ----
    const int r0l = lane >> 2;
    const int c0l = (lane & 3) * 2;
#pragma unroll
    for (int mi = 0; mi < 4; mi++) {
#pragma unroll
        for (int ni = 0; ni < 4; ni++) {
            int gc = n0 + wn * 32 + ni * 8 + c0l;
            float bv0 = __ldg(&bias[(size_t)e * NTOT + gc]);
            float bv1 = __ldg(&bias[(size_t)e * NTOT + gc + 1]);
#pragma unroll
            for (int hh = 0; hh < 2; hh++) {
                int lrow = m0 + wm * 64 + mi * 16 + r0l + hh * 8;
                size_t slot = (size_t)(e * T_TOK) + lrow;
                float v0 = acc[mi][ni][hh * 2 + 0] + bv0;
                float v1 = acc[mi][ni][hh * 2 + 1] + bv1;
                if (GELU) {
                    float q0 = 0.5f * v0 * (1.0f + erff(v0 * 0.70710678118654752f));
                    float q1 = 0.5f * v1 * (1.0f + erff(v1 * 0.70710678118654752f));
                    __half h0 = __float2half_rn(q0), h1 = __float2half_rn(q1);
                    __half l0 = __float2half_rn(q0 - __half2float(h0));
                    __half l1 = __float2half_rn(q1 - __half2float(h1));
                    __half* hp = g_Hh + slot * 8192 + gc;
                    *(__half2*)hp          = __halves2half2(h0, h1);
                    *(__half2*)(hp + 4096) = __halves2half2(l0, l1);
                } else {
                    float2 o = make_float2(v0, v1);
                    *(float2*)(g_Y + slot * CDIM + gc) = o;
                }
            }
        }
    }
}

// ---------------------------------------------------------------------------
__global__ void combine_kernel(float* __restrict__ out) {
    const int t = blockIdx.x;
    const int cidx = threadIdx.x * 4;
    int   s0 = g_pair_slot[t * 2 + 0];
    int   s1 = g_pair_slot[t * 2 + 1];
    float g0 = g_pair_gate[t * 2 + 0];
    float g1 = g_pair_gate[t * 2 + 1];
    float4 y0 = *reinterpret_cast<const float4*>(&g_Y[(size_t)s0 * CDIM + cidx]);
    float4 y1 = *reinterpret_cast<const float4*>(&g_Y[(size_t)s1 * CDIM + cidx]);
    float4 o;
    o.x = g0 * y0.x + g1 * y1.x;
    o.y = g0 * y0.y + g1 * y1.y;
    o.z = g0 * y0.z + g1 * y1.z;
    o.w = g0 * y0.w + g1 * y1.w;
    *reinterpret_cast<float4*>(&out[(size_t)t * CDIM + cidx]) = o;
}

__global__ void loss_kernel(float* __restrict__ out, int out_size) {
    if (threadIdx.x == 0 && out_size > T_TOK * CDIM) {
        float l = 0.0f;
#pragma unroll
        for (int e = 0; e < EDIM; e++) {
            float m = g_gate_sums[e] / (float)T_TOK;
            l += m * logf(m + 1e-8f);
        }
        out[T_TOK * CDIM] = l;
    }
}

// ---------------------------------------------------------------------------
extern "C" void kernel_launch(void* const* d_in, const int* in_sizes, int n_in,
                              void* d_out, int out_size) {
    const float* x      = (const float*)d_in[0];
    const float* gumbel = (const float*)d_in[1];
    const float* gate_w = (const float*)d_in[2];
    const float* gate_b = (const float*)d_in[3];
    const float* w1     = (const float*)d_in[4];
    const float* b1     = (const float*)d_in[5];
    const float* w2     = (const float*)d_in[6];
    const float* b2     = (const float*)d_in[7];
    float* out = (float*)d_out;

    init_kernel<<<1, 32>>>();
    gate_kernel<<<T_TOK, 128>>>(x, gumbel, gate_w, gate_b);
    convert_x_kernel<<<dim3(T_TOK, EDIM), 256>>>(x);
    convert_w_kernel<<<dim3(HDIM / 32, CDIM / 32, EDIM), dim3(32, 8)>>>(w1, CDIM, HDIM, 0);
    convert_w_kernel<<<dim3(CDIM / 32, HDIM / 32, EDIM), dim3(32, 8)>>>(w2, HDIM, CDIM, 1);
    gemm_hmma<true, 32><<<dim3(HDIM / 128, T_TOK / 128, EDIM), 256>>>(b1);   // GEMM1 + GELU
    gemm_hmma<false, 128><<<dim3(CDIM / 128, T_TOK / 128, EDIM), 256>>>(b2); // GEMM2
    combine_kernel<<<T_TOK, 256>>>(out);
    loss_kernel<<<1, 32>>>(out, out_size);
}

// round 6
// speedup vs baseline: 3.4976x; 1.3916x over previous
#include <cuda_runtime.h>
#include <cuda_fp16.h>
#include <math.h>
#include <stdint.h>

#define T_TOK 4096
#define CDIM  1024
#define HDIM  4096
#define EDIM  8

// ---------------- device scratch (allocation-free) ----------------
__device__ float  g_gate_sums[EDIM];
__device__ int    g_cnt[EDIM];
__device__ int    g_bucket_tok[EDIM * T_TOK];
__device__ int    g_pair_slot[T_TOK * 2];
__device__ float  g_pair_gate[T_TOK * 2];
__device__ __half g_Ah [(size_t)EDIM * T_TOK * 2048];   // gathered x: hi[0,1024) lo[1024,2048)
__device__ __half g_Hh [(size_t)EDIM * T_TOK * 8192];   // gelu(h):    hi[0,4096) lo[4096,8192)
__device__ __half g_W1t[(size_t)EDIM * HDIM  * 1024];   // w1^T hi: [E][H][C]
__device__ __half g_W2t[(size_t)EDIM * CDIM  * 4096];   // w2^T hi: [E][C][H]
__device__ float  g_Y  [(size_t)EDIM * T_TOK * CDIM];

// ---------------- helpers ----------------
__device__ __forceinline__ uint32_t smem_u32(const void* p) {
    uint32_t a;
    asm("{ .reg .u64 t; cvta.to.shared.u64 t, %1; cvt.u32.u64 %0, t; }" : "=r"(a) : "l"(p));
    return a;
}
__device__ __forceinline__ void cp_async16(uint32_t dst, const void* src) {
    asm volatile("cp.async.cg.shared.global [%0], [%1], 16;\n" :: "r"(dst), "l"(src));
}
#define CP_COMMIT() asm volatile("cp.async.commit_group;" ::: "memory")
#define CP_WAIT1()  asm volatile("cp.async.wait_group 1;" ::: "memory")

__device__ __forceinline__ void ldmx4(uint32_t& r0, uint32_t& r1, uint32_t& r2, uint32_t& r3,
                                      uint32_t addr) {
    asm volatile("ldmatrix.sync.aligned.m8n8.x4.shared.b16 {%0,%1,%2,%3}, [%4];"
                 : "=r"(r0), "=r"(r1), "=r"(r2), "=r"(r3) : "r"(addr));
}
__device__ __forceinline__ void mma16816(float* d, const uint32_t* a, uint32_t b0, uint32_t b1) {
    asm volatile("mma.sync.aligned.m16n8k16.row.col.f32.f16.f16.f32 "
                 "{%0,%1,%2,%3}, {%4,%5,%6,%7}, {%8,%9}, {%0,%1,%2,%3};"
                 : "+f"(d[0]), "+f"(d[1]), "+f"(d[2]), "+f"(d[3])
                 : "r"(a[0]), "r"(a[1]), "r"(a[2]), "r"(a[3]), "r"(b0), "r"(b1));
}
// byte offset in a [128 rows][32 halves] tile; 16B chunk swizzle: c ^= (r>>1)&3
__device__ __forceinline__ uint32_t sma(int r, int c) {
    return (uint32_t)(((r << 2) | (c ^ ((r >> 1) & 3))) << 4);
}

// ---------------------------------------------------------------------------
__global__ void init_kernel() {
    int i = threadIdx.x;
    if (i < EDIM) { g_gate_sums[i] = 0.0f; g_cnt[i] = 0; }
}

__global__ void gate_kernel(const float* __restrict__ x,
                            const float* __restrict__ gumbel,
                            const float* __restrict__ gw,
                            const float* __restrict__ gb) {
    const int t = blockIdx.x, tid = threadIdx.x;
    float acc[EDIM];
#pragma unroll
    for (int e = 0; e < EDIM; e++) acc[e] = 0.0f;
    const float* xr = x + (size_t)t * CDIM;
    for (int i = tid; i < CDIM; i += 128) {
        float xv = xr[i];
#pragma unroll
        for (int e = 0; e < EDIM; e++) acc[e] += xv * gw[i * EDIM + e];
    }
    __shared__ float red[128][EDIM];
#pragma unroll
    for (int e = 0; e < EDIM; e++) red[tid][e] = acc[e];
    __syncthreads();
    for (int s = 64; s > 0; s >>= 1) {
        if (tid < s) {
#pragma unroll
            for (int e = 0; e < EDIM; e++) red[tid][e] += red[tid + s][e];
        }
        __syncthreads();
    }
    if (tid == 0) {
        float l[EDIM]; float mx = -1e30f;
#pragma unroll
        for (int e = 0; e < EDIM; e++) {
            l[e] = red[0][e] + gb[e] + gumbel[t * EDIM + e];
            mx = fmaxf(mx, l[e]);
        }
        float sum = 0.0f;
#pragma unroll
        for (int e = 0; e < EDIM; e++) { l[e] = expf(l[e] - mx); sum += l[e]; }
        float inv = 1.0f / sum;
        float g[EDIM];
#pragma unroll
        for (int e = 0; e < EDIM; e++) { g[e] = l[e] * inv; atomicAdd(&g_gate_sums[e], g[e]); }
        int i0 = 0;
#pragma unroll
        for (int e = 1; e < EDIM; e++) if (g[e] > g[i0]) i0 = e;
        int i1 = (i0 == 0) ? 1 : 0;
#pragma unroll
        for (int e = 0; e < EDIM; e++) if (e != i0 && g[e] > g[i1]) i1 = e;
        int p0 = atomicAdd(&g_cnt[i0], 1);
        g_bucket_tok[i0 * T_TOK + p0] = t;
        g_pair_slot[t * 2 + 0] = i0 * T_TOK + p0;
        g_pair_gate[t * 2 + 0] = g[i0];
        int p1 = atomicAdd(&g_cnt[i1], 1);
        g_bucket_tok[i1 * T_TOK + p1] = t;
        g_pair_slot[t * 2 + 1] = i1 * T_TOK + p1;
        g_pair_gate[t * 2 + 1] = g[i1];
    }
}

// gather x rows per expert slot -> fp16 hi|lo (zero-pad to 256-row boundary)
__global__ void convert_x_kernel(const float* __restrict__ x) {
    const int e = blockIdx.y, s = blockIdx.x;
    const int cnt = g_cnt[e];
    const int padded = (cnt + 255) & ~255;
    if (s >= padded) return;
    __half* dst = g_Ah + (size_t)(e * T_TOK + s) * 2048;
    const int t = threadIdx.x;  // 256 threads x 4 floats
    if (s < cnt) {
        int tok = g_bucket_tok[e * T_TOK + s];
        float4 v = ((const float4*)(x + (size_t)tok * CDIM))[t];
        __half h0 = __float2half_rn(v.x), h1 = __float2half_rn(v.y);
        __half h2 = __float2half_rn(v.z), h3 = __float2half_rn(v.w);
        ((__half2*)dst)[2 * t + 0] = __halves2half2(h0, h1);
        ((__half2*)dst)[2 * t + 1] = __halves2half2(h2, h3);
        __half l0 = __float2half_rn(v.x - __half2float(h0));
        __half l1 = __float2half_rn(v.y - __half2float(h1));
        __half l2 = __float2half_rn(v.z - __half2float(h2));
        __half l3 = __float2half_rn(v.w - __half2float(h3));
        ((__half2*)(dst + 1024))[2 * t + 0] = __halves2half2(l0, l1);
        ((__half2*)(dst + 1024))[2 * t + 1] = __halves2half2(l2, l3);
    } else {
        __half2 z = __halves2half2(__float2half_rn(0.f), __float2half_rn(0.f));
        ((__half2*)dst)[2 * t + 0] = z;
        ((__half2*)dst)[2 * t + 1] = z;
        ((__half2*)(dst + 1024))[2 * t + 0] = z;
        ((__half2*)(dst + 1024))[2 * t + 1] = z;
    }
}

// transpose + fp16 convert (hi only): in [E][A][Bd] fp32 -> out [E][Bd][A] fp16
__global__ void convert_w_kernel(const float* __restrict__ W, int A, int Bd, int which) {
    __shared__ float s[32][33];
    const int e = blockIdx.z;
    const int a0 = blockIdx.y * 32, b0 = blockIdx.x * 32;
    const int tx = threadIdx.x, ty = threadIdx.y;  // (32, 8)
    const float* Wp = W + (size_t)e * A * Bd;
    __half* Wt = (which ? g_W2t : g_W1t) + (size_t)e * A * Bd;
#pragma unroll
    for (int i = 0; i < 4; i++)
        s[ty * 4 + i][tx] = Wp[(size_t)(a0 + ty * 4 + i) * Bd + b0 + tx];
    __syncthreads();
#pragma unroll
    for (int i = 0; i < 4; i++) {
        float v = s[tx][ty * 4 + i];
        Wt[(size_t)(b0 + ty * 4 + i) * A + a0 + tx] = __float2half_rn(v);
    }
}

// ---------------------------------------------------------------------------
// HMMA grouped GEMM: BM=128, BN=128, BK=32, 256 threads (8 warps, 64x32 warp tiles).
// K' = 2*K region remap: r0 = Ah*Bh, r1 = Al*Bh (A split hi/lo, B hi only).
template<bool GELU, int KB>   // KB = K/32 iters per region
__global__ __launch_bounds__(256, 2) void gemm_hmma(const float* __restrict__ bias) {
    const int e = blockIdx.z;
    const int cnt = g_cnt[e];
    const int m0 = blockIdx.y * 128;
    if (m0 >= cnt) return;
    const int n0 = blockIdx.x * 128;
    const int NK = 2 * KB;

    const int SAA  = GELU ? 2048 : 8192;   // A row stride (halves): hi|lo planes
    const int SB   = GELU ? 1024 : 4096;   // B row stride (halves): hi only
    const int LOFF = GELU ? 1024 : 4096;   // A lo-plane offset
    const int NTOT = GELU ? HDIM : CDIM;
    const __half* __restrict__ abase = GELU ? g_Ah  : g_Hh;
    const __half* __restrict__ bbase = GELU ? g_W1t : g_W2t;

    __shared__ __align__(16) __half smA[3][128 * 32];
    __shared__ __align__(16) __half smB[3][128 * 32];
    const uint32_t aB = smem_u32(&smA[0][0]);
    const uint32_t bB = smem_u32(&smB[0][0]);

    const int tid  = threadIdx.x;
    const int lane = tid & 31;
    const int w    = tid >> 5;
    const int wm   = w & 1;        // 2 m-halves of 64
    const int wn   = w >> 1;       // 4 n-quarters of 32

    const __half* A0 = abase + (size_t)(e * T_TOK + m0) * SAA;
    const __half* B0 = bbase + ((size_t)e * NTOT + n0) * SB;

    float acc[4][4][4];
#pragma unroll
    for (int i = 0; i < 4; i++)
#pragma unroll
        for (int j = 0; j < 4; j++)
#pragma unroll
            for (int q = 0; q < 4; q++) acc[i][j][q] = 0.0f;

    auto load_stage = [&](int kc) {
        const int rg  = kc / KB;
        const int kcl = kc - rg * KB;
        const int ao  = (rg == 1) ? LOFF : 0;
        const int st  = kc % 3;
        const __half* ap = A0 + kcl * 32 + ao;
        const __half* bp = B0 + kcl * 32;
        const uint32_t aS = aB + st * 8192;
        const uint32_t bS = bB + st * 8192;
#pragma unroll
        for (int h = 0; h < 2; h++) {
            int id = tid + h * 256;
            int row = id >> 2, c = id & 3;
            cp_async16(aS + sma(row, c), ap + (size_t)row * SAA + c * 8);
            cp_async16(bS + sma(row, c), bp + (size_t)row * SB + c * 8);
        }
    };

    load_stage(0); CP_COMMIT();
    load_stage(1); CP_COMMIT();

#pragma unroll 1
    for (int kc = 0; kc < NK; kc++) {
        const int s = kc % 3;
        CP_WAIT1();
        __syncthreads();
        if (kc + 2 < NK) load_stage(kc + 2);
        CP_COMMIT();

        const uint32_t aS = aB + s * 8192;
        const uint32_t bS = bB + s * 8192;
#pragma unroll
        for (int ks = 0; ks < 2; ks++) {
            uint32_t afr[4][4];
#pragma unroll
            for (int mi = 0; mi < 4; mi++) {
                int row = wm * 64 + mi * 16 + ((lane >> 3) & 1) * 8 + (lane & 7);
                int ch  = ks * 2 + (lane >> 4);
                ldmx4(afr[mi][0], afr[mi][1], afr[mi][2], afr[mi][3], aS + sma(row, ch));
            }
            uint32_t bfr[2][4];
#pragma unroll
            for (int nj = 0; nj < 2; nj++) {
                int row = wn * 32 + nj * 16 + (lane >> 4) * 8 + (lane & 7);
                int ch  = ks * 2 + ((lane >> 3) & 1);
                ldmx4(bfr[nj][0], bfr[nj][1], bfr[nj][2], bfr[nj][3], bS + sma(row, ch));
            }
#pragma unroll
            for (int mi = 0; mi < 4; mi++)
#pragma unroll
                for (int nj = 0; nj < 2; nj++) {
                    mma16816(acc[mi][nj * 2 + 0], afr[mi], bfr[nj][0], bfr[nj][1]);
                    mma16816(acc[mi][nj * 2 + 1], afr[mi], bfr[nj][2], bfr[nj][3]);
                }
        }
        __syncthreads();
    }

    // ---- epilogue ----
    const int r0l = lane >> 2;
    const int c0l = (lane & 3) * 2;
#pragma unroll
    for (int mi = 0; mi < 4; mi++) {
#pragma unroll
        for (int ni = 0; ni < 4; ni++) {
            int gc = n0 + wn * 32 + ni * 8 + c0l;
            float bv0 = __ldg(&bias[(size_t)e * NTOT + gc]);
            float bv1 = __ldg(&bias[(size_t)e * NTOT + gc + 1]);
#pragma unroll
            for (int hh = 0; hh < 2; hh++) {
                int lrow = m0 + wm * 64 + mi * 16 + r0l + hh * 8;
                size_t slot = (size_t)(e * T_TOK) + lrow;
                float v0 = acc[mi][ni][hh * 2 + 0] + bv0;
                float v1 = acc[mi][ni][hh * 2 + 1] + bv1;
                if (GELU) {
                    float q0 = 0.5f * v0 * (1.0f + erff(v0 * 0.70710678118654752f));
                    float q1 = 0.5f * v1 * (1.0f + erff(v1 * 0.70710678118654752f));
                    __half h0 = __float2half_rn(q0), h1 = __float2half_rn(q1);
                    __half l0 = __float2half_rn(q0 - __half2float(h0));
                    __half l1 = __float2half_rn(q1 - __half2float(h1));
                    __half* hp = g_Hh + slot * 8192 + gc;
                    *(__half2*)hp          = __halves2half2(h0, h1);
                    *(__half2*)(hp + 4096) = __halves2half2(l0, l1);
                } else {
                    float2 o = make_float2(v0, v1);
                    *(float2*)(g_Y + slot * CDIM + gc) = o;
                }
            }
        }
    }
}

// ---------------------------------------------------------------------------
__global__ void combine_kernel(float* __restrict__ out) {
    const int t = blockIdx.x;
    const int cidx = threadIdx.x * 4;
    int   s0 = g_pair_slot[t * 2 + 0];
    int   s1 = g_pair_slot[t * 2 + 1];
    float g0 = g_pair_gate[t * 2 + 0];
    float g1 = g_pair_gate[t * 2 + 1];
    float4 y0 = *reinterpret_cast<const float4*>(&g_Y[(size_t)s0 * CDIM + cidx]);
    float4 y1 = *reinterpret_cast<const float4*>(&g_Y[(size_t)s1 * CDIM + cidx]);
    float4 o;
    o.x = g0 * y0.x + g1 * y1.x;
    o.y = g0 * y0.y + g1 * y1.y;
    o.z = g0 * y0.z + g1 * y1.z;
    o.w = g0 * y0.w + g1 * y1.w;
    *reinterpret_cast<float4*>(&out[(size_t)t * CDIM + cidx]) = o;
}

__global__ void loss_kernel(float* __restrict__ out, int out_size) {
    if (threadIdx.x == 0 && out_size > T_TOK * CDIM) {
        float l = 0.0f;
#pragma unroll
        for (int e = 0; e < EDIM; e++) {
            float m = g_gate_sums[e] / (float)T_TOK;
            l += m * logf(m + 1e-8f);
        }
        out[T_TOK * CDIM] = l;
    }
}

// ---------------------------------------------------------------------------
extern "C" void kernel_launch(void* const* d_in, const int* in_sizes, int n_in,
                              void* d_out, int out_size) {
    const float* x      = (const float*)d_in[0];
    const float* gumbel = (const float*)d_in[1];
    const float* gate_w = (const float*)d_in[2];
    const float* gate_b = (const float*)d_in[3];
    const float* w1     = (const float*)d_in[4];
    const float* b1     = (const float*)d_in[5];
    const float* w2     = (const float*)d_in[6];
    const float* b2     = (const float*)d_in[7];
    float* out = (float*)d_out;

    init_kernel<<<1, 32>>>();
    gate_kernel<<<T_TOK, 128>>>(x, gumbel, gate_w, gate_b);
    convert_x_kernel<<<dim3(T_TOK, EDIM), 256>>>(x);
    convert_w_kernel<<<dim3(HDIM / 32, CDIM / 32, EDIM), dim3(32, 8)>>>(w1, CDIM, HDIM, 0);
    convert_w_kernel<<<dim3(CDIM / 32, HDIM / 32, EDIM), dim3(32, 8)>>>(w2, HDIM, CDIM, 1);
    gemm_hmma<true, 32><<<dim3(HDIM / 128, T_TOK / 128, EDIM), 256>>>(b1);   // GEMM1 + GELU
    gemm_hmma<false, 128><<<dim3(CDIM / 128, T_TOK / 128, EDIM), 256>>>(b2); // GEMM2
    combine_kernel<<<T_TOK, 256>>>(out);
    loss_kernel<<<1, 32>>>(out, out_size);
}

// round 7
// speedup vs baseline: 5.5465x; 1.5858x over previous
#include <cuda_runtime.h>
#include <cuda_fp16.h>
#include <math.h>
#include <stdint.h>

#define T_TOK 4096
#define CDIM  1024
#define HDIM  4096
#define EDIM  8

// ---------------- device scratch (allocation-free) ----------------
__device__ float  g_gate_sums[EDIM];
__device__ int    g_cnt[EDIM];
__device__ int    g_bucket_tok[EDIM * T_TOK];
__device__ int    g_pair_slot[T_TOK * 2];
__device__ float  g_pair_gate[T_TOK * 2];
__device__ __half g_Ah [(size_t)EDIM * T_TOK * CDIM];   // gathered x, fp16
__device__ __half g_Hh [(size_t)EDIM * T_TOK * HDIM];   // gelu(h), fp16
__device__ __half g_W1t[(size_t)EDIM * HDIM  * CDIM];   // w1^T fp16 [E][H][C]
__device__ __half g_W2t[(size_t)EDIM * CDIM  * HDIM];   // w2^T fp16 [E][C][H]
__device__ float  g_Y  [(size_t)EDIM * T_TOK * CDIM];

// ---------------- helpers ----------------
__device__ __forceinline__ uint32_t smem_u32(const void* p) {
    uint32_t a;
    asm("{ .reg .u64 t; cvta.to.shared.u64 t, %1; cvt.u32.u64 %0, t; }" : "=r"(a) : "l"(p));
    return a;
}
__device__ __forceinline__ void cp_async16(uint32_t dst, const void* src) {
    asm volatile("cp.async.cg.shared.global [%0], [%1], 16;\n" :: "r"(dst), "l"(src));
}
#define CP_COMMIT() asm volatile("cp.async.commit_group;" ::: "memory")
#define CP_WAIT1()  asm volatile("cp.async.wait_group 1;" ::: "memory")

__device__ __forceinline__ void ldmx4(uint32_t& r0, uint32_t& r1, uint32_t& r2, uint32_t& r3,
                                      uint32_t addr) {
    asm volatile("ldmatrix.sync.aligned.m8n8.x4.shared.b16 {%0,%1,%2,%3}, [%4];"
                 : "=r"(r0), "=r"(r1), "=r"(r2), "=r"(r3) : "r"(addr));
}
__device__ __forceinline__ void mma16816(float* d, const uint32_t* a, uint32_t b0, uint32_t b1) {
    asm volatile("mma.sync.aligned.m16n8k16.row.col.f32.f16.f16.f32 "
                 "{%0,%1,%2,%3}, {%4,%5,%6,%7}, {%8,%9}, {%0,%1,%2,%3};"
                 : "+f"(d[0]), "+f"(d[1]), "+f"(d[2]), "+f"(d[3])
                 : "r"(a[0]), "r"(a[1]), "r"(a[2]), "r"(a[3]), "r"(b0), "r"(b1));
}
// byte offset in a [128 rows][32 halves] tile; 16B chunk swizzle: c ^= (r>>1)&3
__device__ __forceinline__ uint32_t sma(int r, int c) {
    return (uint32_t)(((r << 2) | (c ^ ((r >> 1) & 3))) << 4);
}

// ---------------------------------------------------------------------------
__global__ void init_kernel() {
    int i = threadIdx.x;
    if (i < EDIM) { g_gate_sums[i] = 0.0f; g_cnt[i] = 0; }
}

__global__ void gate_kernel(const float* __restrict__ x,
                            const float* __restrict__ gumbel,
                            const float* __restrict__ gw,
                            const float* __restrict__ gb) {
    const int t = blockIdx.x, tid = threadIdx.x;
    float acc[EDIM];
#pragma unroll
    for (int e = 0; e < EDIM; e++) acc[e] = 0.0f;
    const float* xr = x + (size_t)t * CDIM;
    for (int i = tid; i < CDIM; i += 128) {
        float xv = xr[i];
#pragma unroll
        for (int e = 0; e < EDIM; e++) acc[e] += xv * gw[i * EDIM + e];
    }
    __shared__ float red[128][EDIM];
#pragma unroll
    for (int e = 0; e < EDIM; e++) red[tid][e] = acc[e];
    __syncthreads();
    for (int s = 64; s > 0; s >>= 1) {
        if (tid < s) {
#pragma unroll
            for (int e = 0; e < EDIM; e++) red[tid][e] += red[tid + s][e];
        }
        __syncthreads();
    }
    if (tid == 0) {
        float l[EDIM]; float mx = -1e30f;
#pragma unroll
        for (int e = 0; e < EDIM; e++) {
            l[e] = red[0][e] + gb[e] + gumbel[t * EDIM + e];
            mx = fmaxf(mx, l[e]);
        }
        float sum = 0.0f;
#pragma unroll
        for (int e = 0; e < EDIM; e++) { l[e] = expf(l[e] - mx); sum += l[e]; }
        float inv = 1.0f / sum;
        float g[EDIM];
#pragma unroll
        for (int e = 0; e < EDIM; e++) { g[e] = l[e] * inv; atomicAdd(&g_gate_sums[e], g[e]); }
        int i0 = 0;
#pragma unroll
        for (int e = 1; e < EDIM; e++) if (g[e] > g[i0]) i0 = e;
        int i1 = (i0 == 0) ? 1 : 0;
#pragma unroll
        for (int e = 0; e < EDIM; e++) if (e != i0 && g[e] > g[i1]) i1 = e;
        int p0 = atomicAdd(&g_cnt[i0], 1);
        g_bucket_tok[i0 * T_TOK + p0] = t;
        g_pair_slot[t * 2 + 0] = i0 * T_TOK + p0;
        g_pair_gate[t * 2 + 0] = g[i0];
        int p1 = atomicAdd(&g_cnt[i1], 1);
        g_bucket_tok[i1 * T_TOK + p1] = t;
        g_pair_slot[t * 2 + 1] = i1 * T_TOK + p1;
        g_pair_gate[t * 2 + 1] = g[i1];
    }
}

// gather x rows per expert slot -> fp16 (zero-pad to 256-row boundary)
__global__ void convert_x_kernel(const float* __restrict__ x) {
    const int e = blockIdx.y, s = blockIdx.x;
    const int cnt = g_cnt[e];
    const int padded = (cnt + 255) & ~255;
    if (s >= padded) return;
    __half* dst = g_Ah + (size_t)(e * T_TOK + s) * CDIM;
    const int t = threadIdx.x;  // 256 threads x 4 floats
    if (s < cnt) {
        int tok = g_bucket_tok[e * T_TOK + s];
        float4 v = ((const float4*)(x + (size_t)tok * CDIM))[t];
        ((__half2*)dst)[2 * t + 0] = __floats2half2_rn(v.x, v.y);
        ((__half2*)dst)[2 * t + 1] = __floats2half2_rn(v.z, v.w);
    } else {
        __half2 z = __floats2half2_rn(0.f, 0.f);
        ((__half2*)dst)[2 * t + 0] = z;
        ((__half2*)dst)[2 * t + 1] = z;
    }
}

// transpose + fp16 convert: in [E][A][Bd] fp32 -> out [E][Bd][A] fp16
__global__ void convert_w_kernel(const float* __restrict__ W, int A, int Bd, int which) {
    __shared__ float s[32][33];
    const int e = blockIdx.z;
    const int a0 = blockIdx.y * 32, b0 = blockIdx.x * 32;
    const int tx = threadIdx.x, ty = threadIdx.y;  // (32, 8)
    const float* Wp = W + (size_t)e * A * Bd;
    __half* Wt = (which ? g_W2t : g_W1t) + (size_t)e * A * Bd;
#pragma unroll
    for (int i = 0; i < 4; i++)
        s[ty * 4 + i][tx] = Wp[(size_t)(a0 + ty * 4 + i) * Bd + b0 + tx];
    __syncthreads();
#pragma unroll
    for (int i = 0; i < 4; i++) {
        float v = s[tx][ty * 4 + i];
        Wt[(size_t)(b0 + ty * 4 + i) * A + a0 + tx] = __float2half_rn(v);
    }
}

// ---------------------------------------------------------------------------
// HMMA grouped GEMM: BM=128, BN=128, BK=32, 256 threads (8 warps, 64x32 warp tiles).
// Plain fp16 operands (no compensated split).
template<bool GELU, int NK>   // NK = K/32
__global__ __launch_bounds__(256, 2) void gemm_hmma(const float* __restrict__ bias) {
    const int e = blockIdx.z;
    const int cnt = g_cnt[e];
    const int m0 = blockIdx.y * 128;
    if (m0 >= cnt) return;
    const int n0 = blockIdx.x * 128;

    const int K    = GELU ? CDIM : HDIM;   // row stride (halves) for A and B
    const int NTOT = GELU ? HDIM : CDIM;
    const __half* __restrict__ abase = GELU ? g_Ah  : g_Hh;
    const __half* __restrict__ bbase = GELU ? g_W1t : g_W2t;

    __shared__ __align__(16) __half smA[3][128 * 32];
    __shared__ __align__(16) __half smB[3][128 * 32];
    const uint32_t aB = smem_u32(&smA[0][0]);
    const uint32_t bB = smem_u32(&smB[0][0]);

    const int tid  = threadIdx.x;
    const int lane = tid & 31;
    const int w    = tid >> 5;
    const int wm   = w & 1;        // 2 m-halves of 64
    const int wn   = w >> 1;       // 4 n-quarters of 32

    const __half* A0 = abase + (size_t)(e * T_TOK + m0) * K;
    const __half* B0 = bbase + ((size_t)e * NTOT + n0) * K;

    float acc[4][4][4];
#pragma unroll
    for (int i = 0; i < 4; i++)
#pragma unroll
        for (int j = 0; j < 4; j++)
#pragma unroll
            for (int q = 0; q < 4; q++) acc[i][j][q] = 0.0f;

    auto load_stage = [&](int kc) {
        const int st = kc % 3;
        const __half* ap = A0 + kc * 32;
        const __half* bp = B0 + kc * 32;
        const uint32_t aS = aB + st * 8192;
        const uint32_t bS = bB + st * 8192;
#pragma unroll
        for (int h = 0; h < 2; h++) {
            int id = tid + h * 256;
            int row = id >> 2, c = id & 3;
            cp_async16(aS + sma(row, c), ap + (size_t)row * K + c * 8);
            cp_async16(bS + sma(row, c), bp + (size_t)row * K + c * 8);
        }
    };

    load_stage(0); CP_COMMIT();
    load_stage(1); CP_COMMIT();

#pragma unroll 1
    for (int kc = 0; kc < NK; kc++) {
        const int s = kc % 3;
        CP_WAIT1();
        __syncthreads();
        if (kc + 2 < NK) load_stage(kc + 2);
        CP_COMMIT();

        const uint32_t aS = aB + s * 8192;
        const uint32_t bS = bB + s * 8192;
#pragma unroll
        for (int ks = 0; ks < 2; ks++) {
            uint32_t afr[4][4];
#pragma unroll
            for (int mi = 0; mi < 4; mi++) {
                int row = wm * 64 + mi * 16 + ((lane >> 3) & 1) * 8 + (lane & 7);
                int ch  = ks * 2 + (lane >> 4);
                ldmx4(afr[mi][0], afr[mi][1], afr[mi][2], afr[mi][3], aS + sma(row, ch));
            }
            uint32_t bfr[2][4];
#pragma unroll
            for (int nj = 0; nj < 2; nj++) {
                int row = wn * 32 + nj * 16 + (lane >> 4) * 8 + (lane & 7);
                int ch  = ks * 2 + ((lane >> 3) & 1);
                ldmx4(bfr[nj][0], bfr[nj][1], bfr[nj][2], bfr[nj][3], bS + sma(row, ch));
            }
#pragma unroll
            for (int mi = 0; mi < 4; mi++)
#pragma unroll
                for (int nj = 0; nj < 2; nj++) {
                    mma16816(acc[mi][nj * 2 + 0], afr[mi], bfr[nj][0], bfr[nj][1]);
                    mma16816(acc[mi][nj * 2 + 1], afr[mi], bfr[nj][2], bfr[nj][3]);
                }
        }
        __syncthreads();
    }

    // ---- epilogue ----
    const int r0l = lane >> 2;
    const int c0l = (lane & 3) * 2;
#pragma unroll
    for (int mi = 0; mi < 4; mi++) {
#pragma unroll
        for (int ni = 0; ni < 4; ni++) {
            int gc = n0 + wn * 32 + ni * 8 + c0l;
            float bv0 = __ldg(&bias[(size_t)e * NTOT + gc]);
            float bv1 = __ldg(&bias[(size_t)e * NTOT + gc + 1]);
#pragma unroll
            for (int hh = 0; hh < 2; hh++) {
                int lrow = m0 + wm * 64 + mi * 16 + r0l + hh * 8;
                size_t slot = (size_t)(e * T_TOK) + lrow;
                float v0 = acc[mi][ni][hh * 2 + 0] + bv0;
                float v1 = acc[mi][ni][hh * 2 + 1] + bv1;
                if (GELU) {
                    float q0 = 0.5f * v0 * (1.0f + erff(v0 * 0.70710678118654752f));
                    float q1 = 0.5f * v1 * (1.0f + erff(v1 * 0.70710678118654752f));
                    *(__half2*)(g_Hh + slot * HDIM + gc) = __floats2half2_rn(q0, q1);
                } else {
                    *(float2*)(g_Y + slot * CDIM + gc) = make_float2(v0, v1);
                }
            }
        }
    }
}

// ---------------------------------------------------------------------------
__global__ void combine_kernel(float* __restrict__ out) {
    const int t = blockIdx.x;
    const int cidx = threadIdx.x * 4;
    int   s0 = g_pair_slot[t * 2 + 0];
    int   s1 = g_pair_slot[t * 2 + 1];
    float g0 = g_pair_gate[t * 2 + 0];
    float g1 = g_pair_gate[t * 2 + 1];
    float4 y0 = *reinterpret_cast<const float4*>(&g_Y[(size_t)s0 * CDIM + cidx]);
    float4 y1 = *reinterpret_cast<const float4*>(&g_Y[(size_t)s1 * CDIM + cidx]);
    float4 o;
    o.x = g0 * y0.x + g1 * y1.x;
    o.y = g0 * y0.y + g1 * y1.y;
    o.z = g0 * y0.z + g1 * y1.z;
    o.w = g0 * y0.w + g1 * y1.w;
    *reinterpret_cast<float4*>(&out[(size_t)t * CDIM + cidx]) = o;
}

__global__ void loss_kernel(float* __restrict__ out, int out_size) {
    if (threadIdx.x == 0 && out_size > T_TOK * CDIM) {
        float l = 0.0f;
#pragma unroll
        for (int e = 0; e < EDIM; e++) {
            float m = g_gate_sums[e] / (float)T_TOK;
            l += m * logf(m + 1e-8f);
        }
        out[T_TOK * CDIM] = l;
    }
}

// ---------------------------------------------------------------------------
extern "C" void kernel_launch(void* const* d_in, const int* in_sizes, int n_in,
                              void* d_out, int out_size) {
    const float* x      = (const float*)d_in[0];
    const float* gumbel = (const float*)d_in[1];
    const float* gate_w = (const float*)d_in[2];
    const float* gate_b = (const float*)d_in[3];
    const float* w1     = (const float*)d_in[4];
    const float* b1     = (const float*)d_in[5];
    const float* w2     = (const float*)d_in[6];
    const float* b2     = (const float*)d_in[7];
    float* out = (float*)d_out;

    init_kernel<<<1, 32>>>();
    gate_kernel<<<T_TOK, 128>>>(x, gumbel, gate_w, gate_b);
    convert_x_kernel<<<dim3(T_TOK, EDIM), 256>>>(x);
    convert_w_kernel<<<dim3(HDIM / 32, CDIM / 32, EDIM), dim3(32, 8)>>>(w1, CDIM, HDIM, 0);
    convert_w_kernel<<<dim3(CDIM / 32, HDIM / 32, EDIM), dim3(32, 8)>>>(w2, HDIM, CDIM, 1);
    gemm_hmma<true, 32><<<dim3(HDIM / 128, T_TOK / 128, EDIM), 256>>>(b1);    // GEMM1 + GELU
    gemm_hmma<false, 128><<<dim3(CDIM / 128, T_TOK / 128, EDIM), 256>>>(b2);  // GEMM2
    combine_kernel<<<T_TOK, 256>>>(out);
    loss_kernel<<<1, 32>>>(out, out_size);
}

// round 8
// speedup vs baseline: 6.1708x; 1.1126x over previous
#include <cuda_runtime.h>
#include <cuda_fp16.h>
#include <math.h>
#include <stdint.h>

#define T_TOK 4096
#define CDIM  1024
#define HDIM  4096
#define EDIM  8

// ---------------- device scratch (allocation-free) ----------------
__device__ float  g_gate_sums[EDIM];
__device__ int    g_cnt[EDIM];
__device__ int    g_bucket_tok[EDIM * T_TOK];
__device__ int    g_pair_slot[T_TOK * 2];
__device__ float  g_pair_gate[T_TOK * 2];
__device__ __half g_Ah [(size_t)EDIM * T_TOK * CDIM];   // gathered x, fp16
__device__ __half g_Hh [(size_t)EDIM * T_TOK * HDIM];   // gelu(h), fp16
__device__ __half g_W1t[(size_t)EDIM * HDIM  * CDIM];   // w1^T fp16 [E][H][C]
__device__ __half g_W2t[(size_t)EDIM * CDIM  * HDIM];   // w2^T fp16 [E][C][H]
__device__ float  g_Y  [(size_t)EDIM * T_TOK * CDIM];

// ---------------- helpers ----------------
__device__ __forceinline__ uint32_t smem_u32(const void* p) {
    uint32_t a;
    asm("{ .reg .u64 t; cvta.to.shared.u64 t, %1; cvt.u32.u64 %0, t; }" : "=r"(a) : "l"(p));
    return a;
}
__device__ __forceinline__ void cp_async16(uint32_t dst, const void* src) {
    asm volatile("cp.async.cg.shared.global [%0], [%1], 16;\n" :: "r"(dst), "l"(src));
}
#define CP_COMMIT() asm volatile("cp.async.commit_group;" ::: "memory")
#define CP_WAIT1()  asm volatile("cp.async.wait_group 1;" ::: "memory")

__device__ __forceinline__ void ldmx4(uint32_t& r0, uint32_t& r1, uint32_t& r2, uint32_t& r3,
                                      uint32_t addr) {
    asm volatile("ldmatrix.sync.aligned.m8n8.x4.shared.b16 {%0,%1,%2,%3}, [%4];"
                 : "=r"(r0), "=r"(r1), "=r"(r2), "=r"(r3) : "r"(addr));
}
__device__ __forceinline__ void mma16816(float* d, const uint32_t* a, uint32_t b0, uint32_t b1) {
    asm volatile("mma.sync.aligned.m16n8k16.row.col.f32.f16.f16.f32 "
                 "{%0,%1,%2,%3}, {%4,%5,%6,%7}, {%8,%9}, {%0,%1,%2,%3};"
                 : "+f"(d[0]), "+f"(d[1]), "+f"(d[2]), "+f"(d[3])
                 : "r"(a[0]), "r"(a[1]), "r"(a[2]), "r"(a[3]), "r"(b0), "r"(b1));
}
// byte offset in a [128 rows][32 halves] tile; 16B chunk swizzle: c ^= (r>>1)&3
__device__ __forceinline__ uint32_t sma(int r, int c) {
    return (uint32_t)(((r << 2) | (c ^ ((r >> 1) & 3))) << 4);
}

// ---------------------------------------------------------------------------
__global__ void init_kernel() {
    int i = threadIdx.x;
    if (i < EDIM) { g_gate_sums[i] = 0.0f; g_cnt[i] = 0; }
}

__global__ void gate_kernel(const float* __restrict__ x,
                            const float* __restrict__ gumbel,
                            const float* __restrict__ gw,
                            const float* __restrict__ gb) {
    const int t = blockIdx.x, tid = threadIdx.x;
    float acc[EDIM];
#pragma unroll
    for (int e = 0; e < EDIM; e++) acc[e] = 0.0f;
    const float* xr = x + (size_t)t * CDIM;
    for (int i = tid; i < CDIM; i += 128) {
        float xv = xr[i];
#pragma unroll
        for (int e = 0; e < EDIM; e++) acc[e] += xv * gw[i * EDIM + e];
    }
    __shared__ float red[128][EDIM];
#pragma unroll
    for (int e = 0; e < EDIM; e++) red[tid][e] = acc[e];
    __syncthreads();
    for (int s = 64; s > 0; s >>= 1) {
        if (tid < s) {
#pragma unroll
            for (int e = 0; e < EDIM; e++) red[tid][e] += red[tid + s][e];
        }
        __syncthreads();
    }
    if (tid == 0) {
        float l[EDIM]; float mx = -1e30f;
#pragma unroll
        for (int e = 0; e < EDIM; e++) {
            l[e] = red[0][e] + gb[e] + gumbel[t * EDIM + e];
            mx = fmaxf(mx, l[e]);
        }
        float sum = 0.0f;
#pragma unroll
        for (int e = 0; e < EDIM; e++) { l[e] = expf(l[e] - mx); sum += l[e]; }
        float inv = 1.0f / sum;
        float g[EDIM];
#pragma unroll
        for (int e = 0; e < EDIM; e++) { g[e] = l[e] * inv; atomicAdd(&g_gate_sums[e], g[e]); }
        int i0 = 0;
#pragma unroll
        for (int e = 1; e < EDIM; e++) if (g[e] > g[i0]) i0 = e;
        int i1 = (i0 == 0) ? 1 : 0;
#pragma unroll
        for (int e = 0; e < EDIM; e++) if (e != i0 && g[e] > g[i1]) i1 = e;
        int p0 = atomicAdd(&g_cnt[i0], 1);
        g_bucket_tok[i0 * T_TOK + p0] = t;
        g_pair_slot[t * 2 + 0] = i0 * T_TOK + p0;
        g_pair_gate[t * 2 + 0] = g[i0];
        int p1 = atomicAdd(&g_cnt[i1], 1);
        g_bucket_tok[i1 * T_TOK + p1] = t;
        g_pair_slot[t * 2 + 1] = i1 * T_TOK + p1;
        g_pair_gate[t * 2 + 1] = g[i1];
    }
}

// gather x rows per expert slot -> fp16 (zero-pad to 256-row boundary)
__global__ void convert_x_kernel(const float* __restrict__ x) {
    const int e = blockIdx.y, s = blockIdx.x;
    const int cnt = g_cnt[e];
    const int padded = (cnt + 255) & ~255;
    if (s >= padded) return;
    __half* dst = g_Ah + (size_t)(e * T_TOK + s) * CDIM;
    const int t = threadIdx.x;  // 256 threads x 4 floats
    if (s < cnt) {
        int tok = g_bucket_tok[e * T_TOK + s];
        float4 v = ((const float4*)(x + (size_t)tok * CDIM))[t];
        ((__half2*)dst)[2 * t + 0] = __floats2half2_rn(v.x, v.y);
        ((__half2*)dst)[2 * t + 1] = __floats2half2_rn(v.z, v.w);
    } else {
        __half2 z = __floats2half2_rn(0.f, 0.f);
        ((__half2*)dst)[2 * t + 0] = z;
        ((__half2*)dst)[2 * t + 1] = z;
    }
}

// transpose + fp16 convert: in [E][A][Bd] fp32 -> out [E][Bd][A] fp16
// Tile: 64 (a) x 32 (b); vectorized half2 stores (contiguous 128B per warp).
__global__ void convert_w_kernel(const float* __restrict__ W, int A, int Bd, int which) {
    __shared__ float s[64][33];
    const int e = blockIdx.z;
    const int a0 = blockIdx.y * 64, b0 = blockIdx.x * 32;
    const int t = threadIdx.x;  // 256
    const float* Wp = W + (size_t)e * A * Bd;
    __half* Wt = (which ? g_W2t : g_W1t) + (size_t)e * A * Bd;
    {
        const int col = t & 31;
        const int r0 = t >> 5;          // 0..7
#pragma unroll
        for (int i = 0; i < 8; i++) {
            int r = r0 + i * 8;
            s[r][col] = Wp[(size_t)(a0 + r) * Bd + b0 + col];
        }
    }
    __syncthreads();
    {
        const int col2 = t & 31;        // half2 index within output row (a-pairs)
        const int bb0  = t >> 5;        // 0..7
#pragma unroll
        for (int j = 0; j < 4; j++) {
            int b = bb0 + j * 8;
            __half2 hv = __floats2half2_rn(s[2 * col2][b], s[2 * col2 + 1][b]);
            *(__half2*)(Wt + (size_t)(b0 + b) * A + a0 + 2 * col2) = hv;
        }
    }
}

// ---------------------------------------------------------------------------
// HMMA grouped GEMM: BM=128, BN=128, BK=32, 128 threads (4 warps, 64x64 warp tiles).
template<bool GELU, int NK>   // NK = K/32
__global__ __launch_bounds__(128, 2) void gemm_hmma(const float* __restrict__ bias) {
    const int e = blockIdx.z;
    const int cnt = g_cnt[e];
    const int m0 = blockIdx.y * 128;
    if (m0 >= cnt) return;
    const int n0 = blockIdx.x * 128;

    const int K    = GELU ? CDIM : HDIM;   // row stride (halves) for A and B
    const int NTOT = GELU ? HDIM : CDIM;
    const __half* __restrict__ abase = GELU ? g_Ah  : g_Hh;
    const __half* __restrict__ bbase = GELU ? g_W1t : g_W2t;

    __shared__ __align__(16) __half smA[3][128 * 32];
    __shared__ __align__(16) __half smB[3][128 * 32];
    const uint32_t aB = smem_u32(&smA[0][0]);
    const uint32_t bB = smem_u32(&smB[0][0]);

    const int tid  = threadIdx.x;
    const int lane = tid & 31;
    const int w    = tid >> 5;
    const int wm   = w & 1;        // m-half of 64
    const int wn   = w >> 1;       // n-half of 64

    const __half* A0 = abase + (size_t)(e * T_TOK + m0) * K;
    const __half* B0 = bbase + ((size_t)e * NTOT + n0) * K;

    float acc[4][8][4];
#pragma unroll
    for (int i = 0; i < 4; i++)
#pragma unroll
        for (int j = 0; j < 8; j++)
#pragma unroll
            for (int q = 0; q < 4; q++) acc[i][j][q] = 0.0f;

    auto load_stage = [&](int kc) {
        const int st = kc % 3;
        const __half* ap = A0 + kc * 32;
        const __half* bp = B0 + kc * 32;
        const uint32_t aS = aB + st * 8192;
        const uint32_t bS = bB + st * 8192;
#pragma unroll
        for (int h = 0; h < 4; h++) {
            int id = tid + h * 128;
            int row = id >> 2, c = id & 3;
            cp_async16(aS + sma(row, c), ap + (size_t)row * K + c * 8);
            cp_async16(bS + sma(row, c), bp + (size_t)row * K + c * 8);
        }
    };

    load_stage(0); CP_COMMIT();
    load_stage(1); CP_COMMIT();

#pragma unroll 1
    for (int kc = 0; kc < NK; kc++) {
        const int s = kc % 3;
        CP_WAIT1();
        __syncthreads();
        if (kc + 2 < NK) load_stage(kc + 2);
        CP_COMMIT();

        const uint32_t aS = aB + s * 8192;
        const uint32_t bS = bB + s * 8192;
#pragma unroll
        for (int ks = 0; ks < 2; ks++) {
            uint32_t afr[4][4];
#pragma unroll
            for (int mi = 0; mi < 4; mi++) {
                int row = wm * 64 + mi * 16 + ((lane >> 3) & 1) * 8 + (lane & 7);
                int ch  = ks * 2 + (lane >> 4);
                ldmx4(afr[mi][0], afr[mi][1], afr[mi][2], afr[mi][3], aS + sma(row, ch));
            }
            uint32_t bfr[4][4];
#pragma unroll
            for (int nj = 0; nj < 4; nj++) {
                int row = wn * 64 + nj * 16 + (lane >> 4) * 8 + (lane & 7);
                int ch  = ks * 2 + ((lane >> 3) & 1);
                ldmx4(bfr[nj][0], bfr[nj][1], bfr[nj][2], bfr[nj][3], bS + sma(row, ch));
            }
#pragma unroll
            for (int mi = 0; mi < 4; mi++)
#pragma unroll
                for (int nj = 0; nj < 4; nj++) {
                    mma16816(acc[mi][nj * 2 + 0], afr[mi], bfr[nj][0], bfr[nj][1]);
                    mma16816(acc[mi][nj * 2 + 1], afr[mi], bfr[nj][2], bfr[nj][3]);
                }
        }
        __syncthreads();
    }

    // ---- epilogue ----
    const int r0l = lane >> 2;
    const int c0l = (lane & 3) * 2;
#pragma unroll
    for (int mi = 0; mi < 4; mi++) {
#pragma unroll
        for (int ni = 0; ni < 8; ni++) {
            int gc = n0 + wn * 64 + ni * 8 + c0l;
            float bv0 = __ldg(&bias[(size_t)e * NTOT + gc]);
            float bv1 = __ldg(&bias[(size_t)e * NTOT + gc + 1]);
#pragma unroll
            for (int hh = 0; hh < 2; hh++) {
                int lrow = m0 + wm * 64 + mi * 16 + r0l + hh * 8;
                size_t slot = (size_t)(e * T_TOK) + lrow;
                float v0 = acc[mi][ni][hh * 2 + 0] + bv0;
                float v1 = acc[mi][ni][hh * 2 + 1] + bv1;
                if (GELU) {
                    float q0 = 0.5f * v0 * (1.0f + erff(v0 * 0.70710678118654752f));
                    float q1 = 0.5f * v1 * (1.0f + erff(v1 * 0.70710678118654752f));
                    *(__half2*)(g_Hh + slot * HDIM + gc) = __floats2half2_rn(q0, q1);
                } else {
                    *(float2*)(g_Y + slot * CDIM + gc) = make_float2(v0, v1);
                }
            }
        }
    }
}

// ---------------------------------------------------------------------------
__global__ void combine_kernel(float* __restrict__ out) {
    const int t = blockIdx.x;
    const int cidx = threadIdx.x * 4;
    int   s0 = g_pair_slot[t * 2 + 0];
    int   s1 = g_pair_slot[t * 2 + 1];
    float g0 = g_pair_gate[t * 2 + 0];
    float g1 = g_pair_gate[t * 2 + 1];
    float4 y0 = *reinterpret_cast<const float4*>(&g_Y[(size_t)s0 * CDIM + cidx]);
    float4 y1 = *reinterpret_cast<const float4*>(&g_Y[(size_t)s1 * CDIM + cidx]);
    float4 o;
    o.x = g0 * y0.x + g1 * y1.x;
    o.y = g0 * y0.y + g1 * y1.y;
    o.z = g0 * y0.z + g1 * y1.z;
    o.w = g0 * y0.w + g1 * y1.w;
    *reinterpret_cast<float4*>(&out[(size_t)t * CDIM + cidx]) = o;
}

__global__ void loss_kernel(float* __restrict__ out, int out_size) {
    if (threadIdx.x == 0 && out_size > T_TOK * CDIM) {
        float l = 0.0f;
#pragma unroll
        for (int e = 0; e < EDIM; e++) {
            float m = g_gate_sums[e] / (float)T_TOK;
            l += m * logf(m + 1e-8f);
        }
        out[T_TOK * CDIM] = l;
    }
}

// ---------------------------------------------------------------------------
extern "C" void kernel_launch(void* const* d_in, const int* in_sizes, int n_in,
                              void* d_out, int out_size) {
    const float* x      = (const float*)d_in[0];
    const float* gumbel = (const float*)d_in[1];
    const float* gate_w = (const float*)d_in[2];
    const float* gate_b = (const float*)d_in[3];
    const float* w1     = (const float*)d_in[4];
    const float* b1     = (const float*)d_in[5];
    const float* w2     = (const float*)d_in[6];
    const float* b2     = (const float*)d_in[7];
    float* out = (float*)d_out;

    init_kernel<<<1, 32>>>();
    gate_kernel<<<T_TOK, 128>>>(x, gumbel, gate_w, gate_b);
    convert_x_kernel<<<dim3(T_TOK, EDIM), 256>>>(x);
    convert_w_kernel<<<dim3(HDIM / 32, CDIM / 64, EDIM), 256>>>(w1, CDIM, HDIM, 0);
    convert_w_kernel<<<dim3(CDIM / 32, HDIM / 64, EDIM), 256>>>(w2, HDIM, CDIM, 1);
    gemm_hmma<true, 32><<<dim3(HDIM / 128, T_TOK / 128, EDIM), 128>>>(b1);    // GEMM1 + GELU
    gemm_hmma<false, 128><<<dim3(CDIM / 128, T_TOK / 128, EDIM), 128>>>(b2);  // GEMM2
    combine_kernel<<<T_TOK, 256>>>(out);
    loss_kernel<<<1, 32>>>(out, out_size);
}